// round 5
// baseline (speedup 1.0000x reference)
#include <cuda_runtime.h>

// Problem constants (fixed by the dataset)
#define E_EDGES 3200000
#define NN      100000
#define G       512
#define F       128      // = HIDDEN
#define NC      10

// ---------------- scratch (no allocations allowed) ----------------
__device__ int   g_is64;                 // 1 if edge_index/batch are int64, else int32
__device__ int   g_hist[G];
__device__ int   g_nhist[G];
__device__ int   g_off[G + 1];
__device__ int   g_noff[G + 1];
__device__ int   g_cursor[G];
__device__ int   g_sorted_src[E_EDGES];
__device__ float g_Sedge[G * F];
__device__ float g_Snode[G * F];
__device__ float g_pooled[G * F];

// Index loads through 4-byte words; for int64 (little-endian, values < 2^31)
// the low word at word-index 2*i is the value.
__device__ __forceinline__ int ld_src(const int* __restrict__ w, int is64, int e) {
    long idx = is64 ? 2L * e : (long)e;
    return w[idx];
}
__device__ __forceinline__ int ld_dst(const int* __restrict__ w, int is64, int e) {
    long idx = is64 ? 2L * ((long)E_EDGES + e) : ((long)E_EDGES + e);
    return w[idx];
}
__device__ __forceinline__ int ld_batch(const int* __restrict__ w, int is64, int i) {
    long idx = is64 ? 2L * i : (long)i;
    return w[idx];
}

// ---------------- kernel 0: dtype detect + zero histograms ----------------
__global__ void init_kernel(const int* __restrict__ ei_w) {
    int t = threadIdx.x;
    if (t < G) { g_hist[t] = 0; g_nhist[t] = 0; }
    if (t == 0) {
        // If int64: odd words are high words == 0 (values in [0,1e5)).
        // If int32: odd words are 64 random values in [0,1e5) — P(all zero) ~ 0.
        int all_zero = 1;
        for (int i = 1; i < 128; i += 2)
            if (ei_w[i] != 0) { all_zero = 0; break; }
        g_is64 = all_zero;
    }
}

// ---------------- kernel 1: edge + node histograms ----------------
// blocks [0,1024): edge histogram of batch[dst[e]]
// blocks [1024,1088): node histogram of batch[i]
__global__ void hist_kernel(const int* __restrict__ ei_w,
                            const int* __restrict__ batch_w) {
    __shared__ int sh[G];
    for (int i = threadIdx.x; i < G; i += blockDim.x) sh[i] = 0;
    __syncthreads();
    int is64 = g_is64;
    int b = blockIdx.x;
    if (b < 1024) {
        for (int e = b * blockDim.x + threadIdx.x; e < E_EDGES;
             e += 1024 * blockDim.x) {
            int d = ld_dst(ei_w, is64, e);
            int g = ld_batch(batch_w, is64, d);
            atomicAdd(&sh[g], 1);
        }
        __syncthreads();
        for (int i = threadIdx.x; i < G; i += blockDim.x)
            if (sh[i]) atomicAdd(&g_hist[i], sh[i]);
    } else {
        int bb = b - 1024;
        for (int i = bb * blockDim.x + threadIdx.x; i < NN; i += 64 * blockDim.x) {
            atomicAdd(&sh[ld_batch(batch_w, is64, i)], 1);
        }
        __syncthreads();
        for (int i = threadIdx.x; i < G; i += blockDim.x)
            if (sh[i]) atomicAdd(&g_nhist[i], sh[i]);
    }
}

// ---------------- kernel 2: exclusive scans (1 block, 512 thr) ----------------
__global__ void scan_kernel() {
    __shared__ int tmp[G];
    int t = threadIdx.x;

    int v = g_hist[t];
    tmp[t] = v; __syncthreads();
    for (int d = 1; d < G; d <<= 1) {
        int u = (t >= d) ? tmp[t - d] : 0;
        __syncthreads();
        tmp[t] += u;
        __syncthreads();
    }
    int excl = tmp[t] - v;
    g_off[t] = excl;
    g_cursor[t] = excl;
    if (t == G - 1) g_off[G] = tmp[t];
    __syncthreads();

    int v2 = g_nhist[t];
    tmp[t] = v2; __syncthreads();
    for (int d = 1; d < G; d <<= 1) {
        int u = (t >= d) ? tmp[t - d] : 0;
        __syncthreads();
        tmp[t] += u;
        __syncthreads();
    }
    g_noff[t] = tmp[t] - v2;
    if (t == G - 1) g_noff[G] = tmp[t];
}

// ---------------- kernel 3: counting-sort scatter of src by graph ----------------
#define SCHUNK 8192
#define STHREADS 256
__global__ void scatter_kernel(const int* __restrict__ ei_w,
                               const int* __restrict__ batch_w) {
    __shared__ unsigned short sh_g[SCHUNK];
    __shared__ int cnt[G];
    __shared__ int base[G];
    int is64 = g_is64;
    int e0 = blockIdx.x * SCHUNK;
    int n = (E_EDGES - e0) < SCHUNK ? (E_EDGES - e0) : SCHUNK;

    for (int i = threadIdx.x; i < G; i += STHREADS) cnt[i] = 0;
    __syncthreads();
    for (int i = threadIdx.x; i < n; i += STHREADS) {
        int d = ld_dst(ei_w, is64, e0 + i);
        int g = ld_batch(batch_w, is64, d);
        sh_g[i] = (unsigned short)g;
        atomicAdd(&cnt[g], 1);
    }
    __syncthreads();
    for (int i = threadIdx.x; i < G; i += STHREADS) {
        int c = cnt[i];
        base[i] = c ? atomicAdd(&g_cursor[i], c) : 0;
        cnt[i] = 0;
    }
    __syncthreads();
    for (int i = threadIdx.x; i < n; i += STHREADS) {
        int g = sh_g[i];
        int r = atomicAdd(&cnt[g], 1);
        g_sorted_src[base[g] + r] = ld_src(ei_w, is64, e0 + i);
    }
}

// ---------------- kernel 4: per-graph feature sums (no atomics) ----------------
// blocks [0,512): S_edge[g] = sum over sorted edges of x[src]
// blocks [512,1024): S_node[g] = sum over contiguous node range of x[i]
#define ACC4(a, v) { (a).x += (v).x; (a).y += (v).y; (a).z += (v).z; (a).w += (v).w; }
__global__ void sum_kernel(const float* __restrict__ x) {
    int b = blockIdx.x;
    int isNode = (b >= G);
    int g = isNode ? (b - G) : b;
    int beg = isNode ? g_noff[g] : g_off[g];
    int end = isNode ? g_noff[g + 1] : g_off[g + 1];
    const float4* __restrict__ x4 = (const float4*)x;
    int warp = threadIdx.x >> 5;   // 8 warps
    int lane = threadIdx.x & 31;   // lane -> features [4*lane, 4*lane+4)

    float4 a0 = make_float4(0, 0, 0, 0), a1 = a0, a2 = a0, a3 = a0;
    int e = beg + warp;
    if (!isNode) {
        for (; e + 24 < end; e += 32) {
            int i0 = __ldg(&g_sorted_src[e]);
            int i1 = __ldg(&g_sorted_src[e + 8]);
            int i2 = __ldg(&g_sorted_src[e + 16]);
            int i3 = __ldg(&g_sorted_src[e + 24]);
            float4 v0 = x4[i0 * 32 + lane];
            float4 v1 = x4[i1 * 32 + lane];
            float4 v2 = x4[i2 * 32 + lane];
            float4 v3 = x4[i3 * 32 + lane];
            ACC4(a0, v0); ACC4(a1, v1); ACC4(a2, v2); ACC4(a3, v3);
        }
        for (; e < end; e += 8) {
            int i0 = __ldg(&g_sorted_src[e]);
            float4 v0 = x4[i0 * 32 + lane];
            ACC4(a0, v0);
        }
    } else {
        for (; e + 24 < end; e += 32) {
            float4 v0 = x4[e * 32 + lane];
            float4 v1 = x4[(e + 8) * 32 + lane];
            float4 v2 = x4[(e + 16) * 32 + lane];
            float4 v3 = x4[(e + 24) * 32 + lane];
            ACC4(a0, v0); ACC4(a1, v1); ACC4(a2, v2); ACC4(a3, v3);
        }
        for (; e < end; e += 8) {
            float4 v0 = x4[e * 32 + lane];
            ACC4(a0, v0);
        }
    }
    ACC4(a0, a1); ACC4(a2, a3); ACC4(a0, a2);

    __shared__ float4 red[8][32];
    red[warp][lane] = a0;
    __syncthreads();
    if (warp == 0) {
        float4 s = red[0][lane];
        #pragma unroll
        for (int w = 1; w < 8; w++) { float4 v = red[w][lane]; ACC4(s, v); }
        float* out = isNode ? g_Snode : g_Sedge;
        ((float4*)out)[g * 32 + lane] = s;
    }
}

// ---------------- kernel 5: pooled = (Se@Wrel + cnt*brel + Sn@Wroot)/max(cnt,1) ----
#define GSUB 4
__global__ void final1_kernel(const float* __restrict__ Wrel,
                              const float* __restrict__ brel,
                              const float* __restrict__ Wroot) {
    __shared__ float se[GSUB][F];
    __shared__ float sn[GSUB][F];
    int t = threadIdx.x;           // 128 threads, t = output hidden index
    int g0 = blockIdx.x * GSUB;
    #pragma unroll
    for (int j = 0; j < GSUB; j++) {
        se[j][t] = g_Sedge[(g0 + j) * F + t];
        sn[j][t] = g_Snode[(g0 + j) * F + t];
    }
    __syncthreads();
    float aR[GSUB] = {0, 0, 0, 0};
    float aO[GSUB] = {0, 0, 0, 0};
    for (int k = 0; k < F; k++) {
        float wr = Wrel[k * F + t];
        float wo = Wroot[k * F + t];
        #pragma unroll
        for (int j = 0; j < GSUB; j++) {
            aR[j] += se[j][k] * wr;
            aO[j] += sn[j][k] * wo;
        }
    }
    float bv = brel[t];
    #pragma unroll
    for (int j = 0; j < GSUB; j++) {
        int g = g0 + j;
        float cnt = (float)g_nhist[g];
        float inv = 1.0f / fmaxf(cnt, 1.0f);
        g_pooled[g * F + t] = (aR[j] + cnt * bv + aO[j]) * inv;
    }
}

// ---------------- kernel 6: out = pooled @ Wlin + blin ----------------
__global__ void final2_kernel(const float* __restrict__ Wlin,
                              const float* __restrict__ blin,
                              float* __restrict__ out) {
    int id = blockIdx.x * blockDim.x + threadIdx.x;
    if (id >= G * NC) return;
    int g = id / NC, c = id % NC;
    float s = blin[c];
    const float* p = &g_pooled[g * F];
    #pragma unroll 8
    for (int h = 0; h < F; h++) s += p[h] * Wlin[h * NC + c];
    out[id] = s;
}

// ---------------- launch ----------------
extern "C" void kernel_launch(void* const* d_in, const int* in_sizes, int n_in,
                              void* d_out, int out_size) {
    const float* x       = (const float*)d_in[0];
    const int*   ei_w    = (const int*)d_in[1];   // [2, E] int32 OR int64 (detected)
    const int*   batch_w = (const int*)d_in[2];   // [N]    int32 OR int64 (detected)
    const float* Wrel    = (const float*)d_in[3];
    const float* brel    = (const float*)d_in[4];
    const float* Wroot   = (const float*)d_in[5];
    const float* Wlin    = (const float*)d_in[6];
    const float* blin    = (const float*)d_in[7];

    init_kernel<<<1, 512>>>(ei_w);
    hist_kernel<<<1088, 256>>>(ei_w, batch_w);
    scan_kernel<<<1, G>>>();
    scatter_kernel<<<(E_EDGES + SCHUNK - 1) / SCHUNK, STHREADS>>>(ei_w, batch_w);
    sum_kernel<<<2 * G, 256>>>(x);
    final1_kernel<<<G / GSUB, F>>>(Wrel, brel, Wroot);
    final2_kernel<<<20, 256>>>(Wlin, blin, (float*)d_out);
}